// round 4
// baseline (speedup 1.0000x reference)
#include <cuda_runtime.h>
#include <cuda_bf16.h>

// Problem dims
#define BB   128
#define TT   512
#define HH   256
#define H2   512
#define LIN  200
#define LPAD 208          // 13 k-tiles * 16
#define FEAT 582
#define FPAD 592          // 37 k-tiles * 16
#define G4   1024
#define SP   58
#define KV   768          // 256 + 512

typedef unsigned long long u64;

// ---------------- device scratch ----------------
__device__ float g_csum [BB * TT * H2];
__device__ float g_feats[BB * TT * FPAD];
__device__ float g_z    [BB * TT * LPAD];
__device__ float g_G0   [BB * TT * G4];
__device__ float g_hs   [BB * TT * HH];
__device__ float g_h    [2 * BB * HH];
__device__ float g_fcW  [LIN * FPAD];     // zero-padded fc_W (16B-aligned rows)
__device__ int   g_lastsep[BB * TT];

#define NB_LSTM 128
__device__ volatile int g_flags[NB_LSTM];

__device__ __forceinline__ float sigf(float x) { return 1.f / (1.f + __expf(-x)); }
__device__ __forceinline__ float tanhfast(float x) {
    float e = __expf(2.f * x);
    return 1.f - 2.f / (e + 1.f);
}

// packed fp32x2 helpers (sm_100+: fma.rn.f32x2)
__device__ __forceinline__ u64 ffma2(u64 a, u64 b, u64 c) {
    u64 d; asm("fma.rn.f32x2 %0, %1, %2, %3;" : "=l"(d) : "l"(a), "l"(b), "l"(c)); return d;
}
__device__ __forceinline__ u64 pack2(float lo, float hi) {
    u64 d; asm("mov.b64 %0, {%1, %2};" : "=l"(d) : "f"(lo), "f"(hi)); return d;
}
__device__ __forceinline__ float2 unpack2(u64 v) {
    float lo, hi; asm("mov.b64 {%0, %1}, %2;" : "=f"(lo), "=f"(hi) : "l"(v));
    return make_float2(lo, hi);
}

// ---------------- kernel 0: pad fc_W rows 582 -> 592 ----------------
__global__ void __launch_bounds__(128) padW_k(const float* __restrict__ W) {
    const int n = blockIdx.x;
    for (int i = threadIdx.x; i < FPAD; i += 128)
        g_fcW[n * FPAD + i] = (i < FEAT) ? W[n * FEAT + i] : 0.f;
}

// ---------------- kernel 1: prefix sums + last-sep scan ----------------
__global__ void __launch_bounds__(128) prep_k(const float* __restrict__ enc,
                                              const int* __restrict__ sep) {
    const int b = blockIdx.x;
    const int ch = blockIdx.y * 128 + threadIdx.x;
    const float* e = enc + (long long)b * TT * H2 + ch;
    float* cs = g_csum + (long long)b * TT * H2 + ch;
    float run = 0.f;
    #pragma unroll 8
    for (int t = 0; t < TT; t++) {
        cs[t * H2] = run;
        run += e[t * H2];
    }
    if (blockIdx.y == 0 && threadIdx.x == 0) {
        int cm = 0;
        const int* sp = sep + b * TT;
        int* ls = g_lastsep + b * TT;
        #pragma unroll 4
        for (int t = 0; t < TT; t++) {
            ls[t] = cm;
            if (sp[t] > 0) cm = t;
        }
    }
}

// ---------------- kernel 2: build features (padded to FPAD with zeros) -------
__global__ void __launch_bounds__(128) feats_k(const int* __restrict__ pos_ids,
                                               const float* __restrict__ pos_emb,
                                               const float* __restrict__ wordlen_emb) {
    const int m = blockIdx.x;             // b*T + t
    const int b = m >> 9;
    const int t = m & (TT - 1);
    const int ls = g_lastsep[m];
    int wlen = t - ls; if (wlen < 1) wlen = 1;
    const int wid = (wlen < 7) ? wlen : 7;
    const int lp = pos_ids[b * TT + ls];
    const float inv = 1.0f / (float)wlen;
    float* f = g_feats + (long long)m * FPAD;
    const float* ct = g_csum + ((long long)b * TT + t) * H2;
    const float* cs = g_csum + ((long long)b * TT + ls) * H2;
    for (int i = threadIdx.x; i < FPAD; i += 128) {
        float v;
        if (i < 50)       v = pos_emb[lp * 50 + i];
        else if (i < 562) { int k = i - 50; v = (ct[k] - cs[k]) * inv; }
        else if (i < 582) v = wordlen_emb[wid * 20 + (i - 562)];
        else              v = 0.f;
        f[i] = v;
    }
}

// ---------------- fp32 GEMM with FFMA2: C[M,N] = A[M,K] * B[N,K]^T ----------
// BM=128, BN=64, BK=16, 128 threads, 8x8 microtile (pairs along m).
// K and ldb must make B rows 16B-aligned and K % 16 == 0 handled via KTAIL.
// MODE 1: fc      (bias1=fc_b, tanh, zero at t==0; pad cols [N,nstore) -> 0)
// MODE 2: ih      (bias1=b_ih, bias2=b_hh)
// MODE 3: combine (A fused hs|enc, mask epilogue)
template<int MODE, bool KMUL16>
__global__ void __launch_bounds__(128) gemm_k(
    const float* __restrict__ A, const float* __restrict__ Bm,
    const float* __restrict__ bias1, const float* __restrict__ bias2,
    const float* __restrict__ enc, const int* __restrict__ length,
    float* __restrict__ C, int N, int K, int lda, int ldb, int ldc, int nstore)
{
    __shared__ __align__(16) float Asm[16][132];
    __shared__ __align__(16) float Bsm[16][72];
    const int n0 = blockIdx.x * 64;
    const int m0 = blockIdx.y * 128;
    const int tid = threadIdx.x;
    const int tx = tid & 7, ty = tid >> 3;

    const int arow = tid >> 2;          // 0..31
    const int akq  = (tid & 3) * 4;     // 0,4,8,12
    const int brow = tid >> 1;          // 0..63
    const int bk0  = (tid & 1) * 8;     // 0 or 8

    u64 acc[4][8];
    #pragma unroll
    for (int p = 0; p < 4; p++)
        #pragma unroll
        for (int q = 0; q < 8; q++) acc[p][q] = 0ull;

    // hoist per-column bias
    float bsum[8];
    #pragma unroll
    for (int q = 0; q < 8; q++) {
        const int n = n0 + tx * 8 + q;
        if (MODE == 1)      bsum[q] = (n < N) ? bias1[n] : 0.f;
        else if (MODE == 2) bsum[q] = bias1[n] + bias2[n];
        else                bsum[q] = 0.f;
    }

    const int nkt = (K + 15) >> 4;

    float4 ra[4], rb[2], na[4], nb[2];

    auto loadA = [&](int kt, float4* r) {
        const int k = kt * 16 + akq;
        #pragma unroll
        for (int p = 0; p < 4; p++) {
            const int m = m0 + arow + p * 32;
            if (MODE == 3) {
                const float* src = (k < 256) ? (A + (long long)m * 256 + k)
                                             : (enc + (long long)m * 512 + (k - 256));
                r[p] = *reinterpret_cast<const float4*>(src);
            } else {
                r[p] = *reinterpret_cast<const float4*>(A + (long long)m * lda + k);
            }
        }
    };
    auto loadB = [&](int kt, float4* r) {
        const int n = n0 + brow;
        #pragma unroll
        for (int q = 0; q < 2; q++) {
            const int k = kt * 16 + bk0 + q * 4;
            float4 v = make_float4(0.f, 0.f, 0.f, 0.f);
            if (n < N) {
                if (KMUL16 || k + 3 < K) {
                    v = *reinterpret_cast<const float4*>(Bm + (long long)n * ldb + k);
                } else {
                    float t4[4];
                    #pragma unroll
                    for (int i = 0; i < 4; i++)
                        t4[i] = (k + i < K) ? Bm[(long long)n * ldb + k + i] : 0.f;
                    v = make_float4(t4[0], t4[1], t4[2], t4[3]);
                }
            }
            r[q] = v;
        }
    };

    loadA(0, ra); loadB(0, rb);
    for (int kt = 0; kt < nkt; kt++) {
        // stage
        #pragma unroll
        for (int p = 0; p < 4; p++) {
            Asm[akq + 0][arow + p * 32] = ra[p].x;
            Asm[akq + 1][arow + p * 32] = ra[p].y;
            Asm[akq + 2][arow + p * 32] = ra[p].z;
            Asm[akq + 3][arow + p * 32] = ra[p].w;
        }
        #pragma unroll
        for (int q = 0; q < 2; q++) {
            Bsm[bk0 + q * 4 + 0][brow] = rb[q].x;
            Bsm[bk0 + q * 4 + 1][brow] = rb[q].y;
            Bsm[bk0 + q * 4 + 2][brow] = rb[q].z;
            Bsm[bk0 + q * 4 + 3][brow] = rb[q].w;
        }
        __syncthreads();
        if (kt + 1 < nkt) { loadA(kt + 1, na); loadB(kt + 1, nb); }
        #pragma unroll
        for (int kk = 0; kk < 16; kk++) {
            const ulonglong2 a01 = *reinterpret_cast<const ulonglong2*>(&Asm[kk][ty * 8]);
            const ulonglong2 a23 = *reinterpret_cast<const ulonglong2*>(&Asm[kk][ty * 8 + 4]);
            const float4 b0 = *reinterpret_cast<const float4*>(&Bsm[kk][tx * 8]);
            const float4 b1 = *reinterpret_cast<const float4*>(&Bsm[kk][tx * 8 + 4]);
            u64 av[4] = {a01.x, a01.y, a23.x, a23.y};
            u64 bd[8] = {pack2(b0.x, b0.x), pack2(b0.y, b0.y), pack2(b0.z, b0.z), pack2(b0.w, b0.w),
                         pack2(b1.x, b1.x), pack2(b1.y, b1.y), pack2(b1.z, b1.z), pack2(b1.w, b1.w)};
            #pragma unroll
            for (int p = 0; p < 4; p++)
                #pragma unroll
                for (int q = 0; q < 8; q++)
                    acc[p][q] = ffma2(av[p], bd[q], acc[p][q]);
        }
        __syncthreads();
        #pragma unroll
        for (int p = 0; p < 4; p++) ra[p] = na[p];
        rb[0] = nb[0]; rb[1] = nb[1];
    }

    // epilogue
    const bool vec = (MODE == 2) || (MODE == 1 && n0 + 64 <= N);
    #pragma unroll
    for (int p = 0; p < 4; p++) {
        float2 fr[8];
        #pragma unroll
        for (int q = 0; q < 8; q++) fr[q] = unpack2(acc[p][q]);
        #pragma unroll
        for (int half = 0; half < 2; half++) {
            const int m = m0 + ty * 8 + p * 2 + half;
            const int t = m & (TT - 1);
            float vals[8];
            int lenb = 0;
            if (MODE == 3) lenb = length[m >> 9];
            #pragma unroll
            for (int q = 0; q < 8; q++) {
                const int n = n0 + tx * 8 + q;
                float v = half ? fr[q].y : fr[q].x;
                if (MODE == 1) {
                    if (n < N) { v = tanhfast(v + bsum[q]); if (t == 0) v = 0.f; }
                    else v = 0.f;   // pad cols
                } else if (MODE == 2) {
                    v += bsum[q];
                } else {
                    if (t >= lenb) v = 0.f;
                    if (t == 0 && n == 0) v = -1e30f;
                }
                vals[q] = v;
            }
            float* cp = C + (long long)m * ldc + n0 + tx * 8;
            if (vec) {
                *reinterpret_cast<float4*>(cp)     = make_float4(vals[0], vals[1], vals[2], vals[3]);
                *reinterpret_cast<float4*>(cp + 4) = make_float4(vals[4], vals[5], vals[6], vals[7]);
            } else {
                #pragma unroll
                for (int q = 0; q < 8; q++) {
                    const int n = n0 + tx * 8 + q;
                    if (n < nstore) cp[q] = vals[q];
                }
            }
        }
    }
}

// ---------------- flag-array grid barrier ----------------
__device__ __forceinline__ void barrier128(int e) {
    __threadfence();
    __syncthreads();
    if (threadIdx.x == 0) g_flags[blockIdx.x] = e;
    while (g_flags[threadIdx.x] < e) { }
    __threadfence();
    __syncthreads();
}

// ---------------- persistent LSTM recurrence (FFMA2) ----------------
// 128 blocks: bt(0..3)*32 batches x ht(0..31)*8 hidden. 128 threads:
// thread = (bg 0..15, jj 0..7) -> 2 batches, 1 hidden, 4 gates.
__global__ void __launch_bounds__(128, 1) lstm_k(const float* __restrict__ W_hh) {
    extern __shared__ float sm[];
    float* Wsm = sm;                 // [32][260]
    float* Hsm = sm + 32 * 260;      // [32][260]
    const int bt = blockIdx.x >> 5;
    const int ht = blockIdx.x & 31;
    const int tid = threadIdx.x;
    const int bg = tid >> 3, jj = tid & 7;
    const int b0 = bt * 32 + bg * 2;
    const int j  = ht * 8 + jj;
    const int e0 = g_flags[blockIdx.x];

    // cache W slice: smem row r = gate(r>>3)*8 + hidden(r&7)
    for (int idx = tid; idx < 2048; idx += 128) {
        const int r = idx >> 6, k4 = idx & 63;
        const int g = r >> 3, hr = r & 7;
        const float4 w = reinterpret_cast<const float4*>(W_hh)[(g * 256 + ht * 8 + hr) * 64 + k4];
        *reinterpret_cast<float4*>(&Wsm[r * 260 + k4 * 4]) = w;
    }
    g_h[b0 * HH + j] = 0.f;
    g_h[(b0 + 1) * HH + j] = 0.f;
    float c0 = 0.f, c1 = 0.f;
    barrier128(e0 + 1);

    const float* Wr0 = &Wsm[(jj     ) * 260];
    const float* Wr1 = &Wsm[( 8 + jj) * 260];
    const float* Wr2 = &Wsm[(16 + jj) * 260];
    const float* Wr3 = &Wsm[(24 + jj) * 260];

    // prefetch G0 for t=0
    float pa[4], pb[4];
    {
        const float* A0 = g_G0 + (long long)(b0 * TT) * G4 + j;
        const float* B0 = g_G0 + (long long)((b0 + 1) * TT) * G4 + j;
        pa[0] = A0[0]; pa[1] = A0[256]; pa[2] = A0[512]; pa[3] = A0[768];
        pb[0] = B0[0]; pb[1] = B0[256]; pb[2] = B0[512]; pb[3] = B0[768];
    }

    for (int t = 0; t < TT; t++) {
        // stage h tile [32 x 256] into smem
        const float* hb = g_h + (t & 1) * (BB * HH) + bt * 32 * HH;
        #pragma unroll
        for (int i = 0; i < 16; i++) {
            const int idx = tid + i * 128;
            const int r = idx >> 6, k4 = idx & 63;
            *reinterpret_cast<float4*>(&Hsm[r * 260 + k4 * 4]) =
                reinterpret_cast<const float4*>(hb)[r * 64 + k4];
        }
        // init accumulators from prefetched G0, then prefetch next step
        u64 acc0[4], acc1[4];
        #pragma unroll
        for (int g = 0; g < 4; g++) { acc0[g] = pack2(pa[g], 0.f); acc1[g] = pack2(pb[g], 0.f); }
        if (t + 1 < TT) {
            const float* A0 = g_G0 + (long long)(b0 * TT + t + 1) * G4 + j;
            const float* B0 = g_G0 + (long long)((b0 + 1) * TT + t + 1) * G4 + j;
            pa[0] = A0[0]; pa[1] = A0[256]; pa[2] = A0[512]; pa[3] = A0[768];
            pb[0] = B0[0]; pb[1] = B0[256]; pb[2] = B0[512]; pb[3] = B0[768];
        }
        __syncthreads();

        const float* H0 = &Hsm[(bg * 2) * 260];
        const float* H1 = H0 + 260;
        #pragma unroll 16
        for (int k4 = 0; k4 < 64; k4++) {
            const ulonglong2 h0 = *reinterpret_cast<const ulonglong2*>(H0 + k4 * 4);
            const ulonglong2 h1 = *reinterpret_cast<const ulonglong2*>(H1 + k4 * 4);
            ulonglong2 w;
            w = *reinterpret_cast<const ulonglong2*>(Wr0 + k4 * 4);
            acc0[0] = ffma2(h0.x, w.x, acc0[0]); acc0[0] = ffma2(h0.y, w.y, acc0[0]);
            acc1[0] = ffma2(h1.x, w.x, acc1[0]); acc1[0] = ffma2(h1.y, w.y, acc1[0]);
            w = *reinterpret_cast<const ulonglong2*>(Wr1 + k4 * 4);
            acc0[1] = ffma2(h0.x, w.x, acc0[1]); acc0[1] = ffma2(h0.y, w.y, acc0[1]);
            acc1[1] = ffma2(h1.x, w.x, acc1[1]); acc1[1] = ffma2(h1.y, w.y, acc1[1]);
            w = *reinterpret_cast<const ulonglong2*>(Wr2 + k4 * 4);
            acc0[2] = ffma2(h0.x, w.x, acc0[2]); acc0[2] = ffma2(h0.y, w.y, acc0[2]);
            acc1[2] = ffma2(h1.x, w.x, acc1[2]); acc1[2] = ffma2(h1.y, w.y, acc1[2]);
            w = *reinterpret_cast<const ulonglong2*>(Wr3 + k4 * 4);
            acc0[3] = ffma2(h0.x, w.x, acc0[3]); acc0[3] = ffma2(h0.y, w.y, acc0[3]);
            acc1[3] = ffma2(h1.x, w.x, acc1[3]); acc1[3] = ffma2(h1.y, w.y, acc1[3]);
        }
        // horizontal reduce + gates (torch order i, f, g, o)
        float s0[4], s1[4];
        #pragma unroll
        for (int g = 0; g < 4; g++) {
            const float2 f0 = unpack2(acc0[g]); s0[g] = f0.x + f0.y;
            const float2 f1 = unpack2(acc1[g]); s1[g] = f1.x + f1.y;
        }
        const float i0 = sigf(s0[0]), f0 = sigf(s0[1]), gg0 = tanhfast(s0[2]), o0 = sigf(s0[3]);
        c0 = f0 * c0 + i0 * gg0;
        const float hv0 = o0 * tanhfast(c0);
        const float i1 = sigf(s1[0]), f1 = sigf(s1[1]), gg1 = tanhfast(s1[2]), o1 = sigf(s1[3]);
        c1 = f1 * c1 + i1 * gg1;
        const float hv1 = o1 * tanhfast(c1);

        g_hs[(long long)(b0 * TT + t) * HH + j] = hv0;
        g_hs[(long long)((b0 + 1) * TT + t) * HH + j] = hv1;
        float* hn = g_h + ((t + 1) & 1) * (BB * HH);
        hn[b0 * HH + j] = hv0;
        hn[(b0 + 1) * HH + j] = hv1;
        barrier128(e0 + 2 + t);
    }
}

// ---------------- host launch ----------------
extern "C" void kernel_launch(void* const* d_in, const int* in_sizes, int n_in,
                              void* d_out, int out_size) {
    const float* enc         = (const float*)d_in[0];
    const int*   sep_mask    = (const int*)d_in[1];
    const int*   pos_ids     = (const int*)d_in[2];
    const int*   length      = (const int*)d_in[3];
    const float* pos_emb     = (const float*)d_in[4];
    const float* wordlen_emb = (const float*)d_in[5];
    const float* fc_W        = (const float*)d_in[6];
    const float* fc_b        = (const float*)d_in[7];
    const float* W_ih        = (const float*)d_in[8];
    const float* W_hh        = (const float*)d_in[9];
    const float* b_ih        = (const float*)d_in[10];
    const float* b_hh        = (const float*)d_in[11];
    const float* combine_W   = (const float*)d_in[12];
    float* out = (float*)d_out;

    float* d_feats; cudaGetSymbolAddress((void**)&d_feats, g_feats);
    float* d_fcW;   cudaGetSymbolAddress((void**)&d_fcW, g_fcW);
    float* d_z;     cudaGetSymbolAddress((void**)&d_z, g_z);
    float* d_G0;    cudaGetSymbolAddress((void**)&d_G0, g_G0);
    float* d_hs;    cudaGetSymbolAddress((void**)&d_hs, g_hs);

    padW_k<<<LIN, 128>>>(fc_W);
    prep_k<<<dim3(BB, 4), 128>>>(enc, sep_mask);
    feats_k<<<BB * TT, 128>>>(pos_ids, pos_emb, wordlen_emb);

    // GEMM1: z = tanh(feats @ g_fcW^T + fc_b)  M=65536 N=200 K=592(padded)
    gemm_k<1, true><<<dim3(4, 512), 128>>>(
        d_feats, d_fcW, fc_b, nullptr, nullptr, nullptr, d_z,
        LIN, FPAD, FPAD, FPAD, LPAD, LPAD);

    // GEMM2: G0 = z @ W_ih^T + b_ih + b_hh     M=65536 N=1024 K=200 (ldb=200: 800B rows, 16B ok)
    gemm_k<2, false><<<dim3(16, 512), 128>>>(
        d_z, W_ih, b_ih, b_hh, nullptr, nullptr, d_G0,
        G4, LIN, LPAD, LIN, G4, G4);

    // LSTM recurrence (persistent, flag barrier, FFMA2)
    const int lstm_smem = 2 * 32 * 260 * (int)sizeof(float);
    cudaFuncSetAttribute(lstm_k, cudaFuncAttributeMaxDynamicSharedMemorySize, lstm_smem);
    lstm_k<<<NB_LSTM, 128, lstm_smem>>>(W_hh);

    // GEMM3: logits = [hs|enc] @ combine_W^T + mask   M=65536 N=58 K=768
    gemm_k<3, true><<<dim3(1, 512), 128>>>(
        d_hs, combine_W, nullptr, nullptr, enc, length, out,
        SP, KV, 0, KV, SP, SP);
}

// round 6
// speedup vs baseline: 1.3838x; 1.3838x over previous
#include <cuda_runtime.h>
#include <cuda_bf16.h>

// Problem dims
#define BB   128
#define TT   512
#define HH   256
#define H2   512
#define LIN  200
#define LPAD 208          // 13 k-tiles * 16
#define FEAT 582
#define FPAD 592          // 37 k-tiles * 16
#define G4   1024
#define SP   58
#define KV   768          // 256 + 512

typedef unsigned long long u64;

// ---------------- device scratch ----------------
__device__ float g_csum [BB * TT * H2];
__device__ float g_feats[BB * TT * FPAD];
__device__ float g_z    [BB * TT * LPAD];
__device__ float g_G0   [BB * TT * G4];
__device__ float g_hs   [BB * TT * HH];
__device__ float g_h    [2 * BB * HH];
__device__ float g_fcW  [LIN * FPAD];     // zero-padded fc_W (16B-aligned rows)
__device__ int   g_lastsep[BB * TT];

#define NB_LSTM 128
#define NBAR    513                         // barriers per launch
__device__ u64 g_count;                     // monotonically increasing across replays

__device__ __forceinline__ float sigf(float x) { return 1.f / (1.f + __expf(-x)); }
__device__ __forceinline__ float tanhfast(float x) {
    float e = __expf(2.f * x);
    return 1.f - 2.f / (e + 1.f);
}

// packed fp32x2 helpers (sm_100+: fma.rn.f32x2)
__device__ __forceinline__ u64 ffma2(u64 a, u64 b, u64 c) {
    u64 d; asm("fma.rn.f32x2 %0, %1, %2, %3;" : "=l"(d) : "l"(a), "l"(b), "l"(c)); return d;
}
__device__ __forceinline__ u64 pack2(float lo, float hi) {
    u64 d; asm("mov.b64 %0, {%1, %2};" : "=l"(d) : "f"(lo), "f"(hi)); return d;
}
__device__ __forceinline__ float2 unpack2(u64 v) {
    float lo, hi; asm("mov.b64 {%0, %1}, %2;" : "=f"(lo), "=f"(hi) : "l"(v));
    return make_float2(lo, hi);
}

// ---------------- kernel 0: pad fc_W rows 582 -> 592 ----------------
__global__ void __launch_bounds__(128) padW_k(const float* __restrict__ W) {
    const int n = blockIdx.x;
    for (int i = threadIdx.x; i < FPAD; i += 128)
        g_fcW[n * FPAD + i] = (i < FEAT) ? W[n * FEAT + i] : 0.f;
}

// ---------------- kernel 1: prefix sums + last-sep scan ----------------
__global__ void __launch_bounds__(128) prep_k(const float* __restrict__ enc,
                                              const int* __restrict__ sep) {
    const int b = blockIdx.x;
    const int ch = blockIdx.y * 128 + threadIdx.x;
    const float* e = enc + (long long)b * TT * H2 + ch;
    float* cs = g_csum + (long long)b * TT * H2 + ch;
    float run = 0.f;
    #pragma unroll 8
    for (int t = 0; t < TT; t++) {
        cs[t * H2] = run;
        run += e[t * H2];
    }
    if (blockIdx.y == 0 && threadIdx.x == 0) {
        int cm = 0;
        const int* sp = sep + b * TT;
        int* ls = g_lastsep + b * TT;
        #pragma unroll 4
        for (int t = 0; t < TT; t++) {
            ls[t] = cm;
            if (sp[t] > 0) cm = t;
        }
    }
}

// ---------------- kernel 2: build features (padded to FPAD with zeros) -------
__global__ void __launch_bounds__(128) feats_k(const int* __restrict__ pos_ids,
                                               const float* __restrict__ pos_emb,
                                               const float* __restrict__ wordlen_emb) {
    const int m = blockIdx.x;             // b*T + t
    const int b = m >> 9;
    const int t = m & (TT - 1);
    const int ls = g_lastsep[m];
    int wlen = t - ls; if (wlen < 1) wlen = 1;
    const int wid = (wlen < 7) ? wlen : 7;
    const int lp = pos_ids[b * TT + ls];
    const float inv = 1.0f / (float)wlen;
    float* f = g_feats + (long long)m * FPAD;
    const float* ct = g_csum + ((long long)b * TT + t) * H2;
    const float* cs = g_csum + ((long long)b * TT + ls) * H2;
    for (int i = threadIdx.x; i < FPAD; i += 128) {
        float v;
        if (i < 50)       v = pos_emb[lp * 50 + i];
        else if (i < 562) { int k = i - 50; v = (ct[k] - cs[k]) * inv; }
        else if (i < 582) v = wordlen_emb[wid * 20 + (i - 562)];
        else              v = 0.f;
        f[i] = v;
    }
}

// ---------------- fp32 GEMM with FFMA2: C[M,N] = A[M,K] * B[N,K]^T ----------
// BM=128, BN=64, BK=16, 128 threads, 8x8 microtile (pairs along m).
// MODE 1: fc      (bias1=fc_b, tanh, zero at t==0; pad cols [N,nstore) -> 0)
// MODE 2: ih      (bias1=b_ih, bias2=b_hh)
// MODE 3: combine (A fused hs|enc, mask epilogue)
template<int MODE, bool KMUL16>
__global__ void __launch_bounds__(128) gemm_k(
    const float* __restrict__ A, const float* __restrict__ Bm,
    const float* __restrict__ bias1, const float* __restrict__ bias2,
    const float* __restrict__ enc, const int* __restrict__ length,
    float* __restrict__ C, int N, int K, int lda, int ldb, int ldc, int nstore)
{
    __shared__ __align__(16) float Asm[16][132];
    __shared__ __align__(16) float Bsm[16][72];
    const int n0 = blockIdx.x * 64;
    const int m0 = blockIdx.y * 128;
    const int tid = threadIdx.x;
    const int tx = tid & 7, ty = tid >> 3;

    const int arow = tid >> 2;          // 0..31
    const int akq  = (tid & 3) * 4;     // 0,4,8,12
    const int brow = tid >> 1;          // 0..63
    const int bk0  = (tid & 1) * 8;     // 0 or 8

    u64 acc[4][8];
    #pragma unroll
    for (int p = 0; p < 4; p++)
        #pragma unroll
        for (int q = 0; q < 8; q++) acc[p][q] = 0ull;

    // hoist per-column bias
    float bsum[8];
    #pragma unroll
    for (int q = 0; q < 8; q++) {
        const int n = n0 + tx * 8 + q;
        if (MODE == 1)      bsum[q] = (n < N) ? bias1[n] : 0.f;
        else if (MODE == 2) bsum[q] = bias1[n] + bias2[n];
        else                bsum[q] = 0.f;
    }

    const int nkt = (K + 15) >> 4;

    float4 ra[4], rb[2], na[4], nb[2];

    auto loadA = [&](int kt, float4* r) {
        const int k = kt * 16 + akq;
        #pragma unroll
        for (int p = 0; p < 4; p++) {
            const int m = m0 + arow + p * 32;
            if (MODE == 3) {
                const float* src = (k < 256) ? (A + (long long)m * 256 + k)
                                             : (enc + (long long)m * 512 + (k - 256));
                r[p] = *reinterpret_cast<const float4*>(src);
            } else {
                r[p] = *reinterpret_cast<const float4*>(A + (long long)m * lda + k);
            }
        }
    };
    auto loadB = [&](int kt, float4* r) {
        const int n = n0 + brow;
        #pragma unroll
        for (int q = 0; q < 2; q++) {
            const int k = kt * 16 + bk0 + q * 4;
            float4 v = make_float4(0.f, 0.f, 0.f, 0.f);
            if (n < N) {
                if (KMUL16 || k + 3 < K) {
                    v = *reinterpret_cast<const float4*>(Bm + (long long)n * ldb + k);
                } else {
                    float t4[4];
                    #pragma unroll
                    for (int i = 0; i < 4; i++)
                        t4[i] = (k + i < K) ? Bm[(long long)n * ldb + k + i] : 0.f;
                    v = make_float4(t4[0], t4[1], t4[2], t4[3]);
                }
            }
            r[q] = v;
        }
    };

    loadA(0, ra); loadB(0, rb);
    for (int kt = 0; kt < nkt; kt++) {
        // stage
        #pragma unroll
        for (int p = 0; p < 4; p++) {
            Asm[akq + 0][arow + p * 32] = ra[p].x;
            Asm[akq + 1][arow + p * 32] = ra[p].y;
            Asm[akq + 2][arow + p * 32] = ra[p].z;
            Asm[akq + 3][arow + p * 32] = ra[p].w;
        }
        #pragma unroll
        for (int q = 0; q < 2; q++) {
            Bsm[bk0 + q * 4 + 0][brow] = rb[q].x;
            Bsm[bk0 + q * 4 + 1][brow] = rb[q].y;
            Bsm[bk0 + q * 4 + 2][brow] = rb[q].z;
            Bsm[bk0 + q * 4 + 3][brow] = rb[q].w;
        }
        __syncthreads();
        if (kt + 1 < nkt) { loadA(kt + 1, na); loadB(kt + 1, nb); }
        #pragma unroll
        for (int kk = 0; kk < 16; kk++) {
            const ulonglong2 a01 = *reinterpret_cast<const ulonglong2*>(&Asm[kk][ty * 8]);
            const ulonglong2 a23 = *reinterpret_cast<const ulonglong2*>(&Asm[kk][ty * 8 + 4]);
            const float4 b0 = *reinterpret_cast<const float4*>(&Bsm[kk][tx * 8]);
            const float4 b1 = *reinterpret_cast<const float4*>(&Bsm[kk][tx * 8 + 4]);
            u64 av[4] = {a01.x, a01.y, a23.x, a23.y};
            u64 bd[8] = {pack2(b0.x, b0.x), pack2(b0.y, b0.y), pack2(b0.z, b0.z), pack2(b0.w, b0.w),
                         pack2(b1.x, b1.x), pack2(b1.y, b1.y), pack2(b1.z, b1.z), pack2(b1.w, b1.w)};
            #pragma unroll
            for (int p = 0; p < 4; p++)
                #pragma unroll
                for (int q = 0; q < 8; q++)
                    acc[p][q] = ffma2(av[p], bd[q], acc[p][q]);
        }
        __syncthreads();
        #pragma unroll
        for (int p = 0; p < 4; p++) ra[p] = na[p];
        rb[0] = nb[0]; rb[1] = nb[1];
    }

    // epilogue
    const bool vec = (MODE == 2) || (MODE == 1 && n0 + 64 <= N);
    #pragma unroll
    for (int p = 0; p < 4; p++) {
        float2 fr[8];
        #pragma unroll
        for (int q = 0; q < 8; q++) fr[q] = unpack2(acc[p][q]);
        #pragma unroll
        for (int half = 0; half < 2; half++) {
            const int m = m0 + ty * 8 + p * 2 + half;
            const int t = m & (TT - 1);
            float vals[8];
            int lenb = 0;
            if (MODE == 3) lenb = length[m >> 9];
            #pragma unroll
            for (int q = 0; q < 8; q++) {
                const int n = n0 + tx * 8 + q;
                float v = half ? fr[q].y : fr[q].x;
                if (MODE == 1) {
                    if (n < N) { v = tanhfast(v + bsum[q]); if (t == 0) v = 0.f; }
                    else v = 0.f;   // pad cols
                } else if (MODE == 2) {
                    v += bsum[q];
                } else {
                    if (t >= lenb) v = 0.f;
                    if (t == 0 && n == 0) v = -1e30f;
                }
                vals[q] = v;
            }
            float* cp = C + (long long)m * ldc + n0 + tx * 8;
            if (vec) {
                *reinterpret_cast<float4*>(cp)     = make_float4(vals[0], vals[1], vals[2], vals[3]);
                *reinterpret_cast<float4*>(cp + 4) = make_float4(vals[4], vals[5], vals[6], vals[7]);
            } else {
                #pragma unroll
                for (int q = 0; q < 8; q++) {
                    const int n = n0 + tx * 8 + q;
                    if (n < nstore) cp[q] = vals[q];
                }
            }
        }
    }
}

// ---------------- grid barrier: RED arrival + single-poller -----------------
__device__ __forceinline__ void gbar(u64 base, int e) {
    __threadfence();
    __syncthreads();
    if (threadIdx.x == 0) {
        atomicAdd(&g_count, 1ULL);               // result unused -> REDG
        const u64 tgt = base + (u64)e * (u64)NB_LSTM;
        while (*(volatile u64*)&g_count < tgt) { }
        __threadfence();
    }
    __syncthreads();
}

// ---------------- persistent LSTM recurrence (FFMA2) ----------------
// 128 blocks: bt(0..3)*32 batches x ht(0..31)*8 hidden.
// 256 threads: thread = (bg 0..31 batch, jj 0..7 hidden) -> 4 gate dots.
__global__ void __launch_bounds__(256, 1) lstm_k(const float* __restrict__ W_hh) {
    extern __shared__ float sm[];
    float* Wsm = sm;                 // [32][260] rows: gate*8 + jj
    float* Hsm = sm + 32 * 260;      // [32][260] rows: batch-in-tile
    __shared__ u64 s_base;
    const int bt = blockIdx.x >> 5;
    const int ht = blockIdx.x & 31;
    const int tid = threadIdx.x;
    const int bg = tid >> 3, jj = tid & 7;
    const int b = bt * 32 + bg;
    const int j = ht * 8 + jj;

    if (tid == 0) {
        const u64 c0 = *(volatile u64*)&g_count;
        s_base = c0 - (c0 % (u64)(NBAR * NB_LSTM));
    }
    // cache W slice: smem row r = gate(r>>3)*8 + hidden(r&7)
    #pragma unroll
    for (int i = 0; i < 8; i++) {
        const int idx = tid + i * 256;
        const int r = idx >> 6, k4 = idx & 63;
        const int g = r >> 3, hr = r & 7;
        const float4 w = reinterpret_cast<const float4*>(W_hh)[(g * 256 + ht * 8 + hr) * 64 + k4];
        *reinterpret_cast<float4*>(&Wsm[r * 260 + k4 * 4]) = w;
    }
    g_h[b * HH + j] = 0.f;
    float c = 0.f;

    // prefetch G0 for t=0
    float pg[4];
    {
        const float* G = g_G0 + (long long)(b * TT) * G4 + j;
        pg[0] = G[0]; pg[1] = G[256]; pg[2] = G[512]; pg[3] = G[768];
    }
    __syncthreads();
    const u64 base = s_base;
    gbar(base, 1);

    const float* Wr0 = &Wsm[(jj     ) * 260];
    const float* Wr1 = &Wsm[( 8 + jj) * 260];
    const float* Wr2 = &Wsm[(16 + jj) * 260];
    const float* Wr3 = &Wsm[(24 + jj) * 260];
    const float* Hr  = &Hsm[bg * 260];

    for (int t = 0; t < TT; t++) {
        // stage h tile [32 x 256] into smem
        const float* hb = g_h + (t & 1) * (BB * HH) + bt * 32 * HH;
        #pragma unroll
        for (int i = 0; i < 8; i++) {
            const int idx = tid + i * 256;
            const int r = idx >> 6, k4 = idx & 63;
            *reinterpret_cast<float4*>(&Hsm[r * 260 + k4 * 4]) =
                reinterpret_cast<const float4*>(hb)[r * 64 + k4];
        }
        u64 acc0 = pack2(pg[0], 0.f);
        u64 acc1 = pack2(pg[1], 0.f);
        u64 acc2 = pack2(pg[2], 0.f);
        u64 acc3 = pack2(pg[3], 0.f);
        if (t + 1 < TT) {
            const float* G = g_G0 + (long long)(b * TT + t + 1) * G4 + j;
            pg[0] = G[0]; pg[1] = G[256]; pg[2] = G[512]; pg[3] = G[768];
        }
        __syncthreads();

        #pragma unroll 16
        for (int k4 = 0; k4 < 64; k4++) {
            const ulonglong2 h2 = *reinterpret_cast<const ulonglong2*>(Hr + k4 * 4);
            ulonglong2 w;
            w = *reinterpret_cast<const ulonglong2*>(Wr0 + k4 * 4);
            acc0 = ffma2(h2.x, w.x, acc0); acc0 = ffma2(h2.y, w.y, acc0);
            w = *reinterpret_cast<const ulonglong2*>(Wr1 + k4 * 4);
            acc1 = ffma2(h2.x, w.x, acc1); acc1 = ffma2(h2.y, w.y, acc1);
            w = *reinterpret_cast<const ulonglong2*>(Wr2 + k4 * 4);
            acc2 = ffma2(h2.x, w.x, acc2); acc2 = ffma2(h2.y, w.y, acc2);
            w = *reinterpret_cast<const ulonglong2*>(Wr3 + k4 * 4);
            acc3 = ffma2(h2.x, w.x, acc3); acc3 = ffma2(h2.y, w.y, acc3);
        }
        const float2 r0 = unpack2(acc0);
        const float2 r1 = unpack2(acc1);
        const float2 r2 = unpack2(acc2);
        const float2 r3 = unpack2(acc3);
        const float gi = sigf(r0.x + r0.y);
        const float gf = sigf(r1.x + r1.y);
        const float gg = tanhfast(r2.x + r2.y);
        const float go = sigf(r3.x + r3.y);
        c = gf * c + gi * gg;
        const float hv = go * tanhfast(c);

        g_hs[(long long)(b * TT + t) * HH + j] = hv;
        g_h[((t + 1) & 1) * (BB * HH) + b * HH + j] = hv;
        gbar(base, 2 + t);
    }
}

// ---------------- host launch ----------------
extern "C" void kernel_launch(void* const* d_in, const int* in_sizes, int n_in,
                              void* d_out, int out_size) {
    const float* enc         = (const float*)d_in[0];
    const int*   sep_mask    = (const int*)d_in[1];
    const int*   pos_ids     = (const int*)d_in[2];
    const int*   length      = (const int*)d_in[3];
    const float* pos_emb     = (const float*)d_in[4];
    const float* wordlen_emb = (const float*)d_in[5];
    const float* fc_W        = (const float*)d_in[6];
    const float* fc_b        = (const float*)d_in[7];
    const float* W_ih        = (const float*)d_in[8];
    const float* W_hh        = (const float*)d_in[9];
    const float* b_ih        = (const float*)d_in[10];
    const float* b_hh        = (const float*)d_in[11];
    const float* combine_W   = (const float*)d_in[12];
    float* out = (float*)d_out;

    float* d_feats; cudaGetSymbolAddress((void**)&d_feats, g_feats);
    float* d_fcW;   cudaGetSymbolAddress((void**)&d_fcW, g_fcW);
    float* d_z;     cudaGetSymbolAddress((void**)&d_z, g_z);
    float* d_G0;    cudaGetSymbolAddress((void**)&d_G0, g_G0);
    float* d_hs;    cudaGetSymbolAddress((void**)&d_hs, g_hs);

    padW_k<<<LIN, 128>>>(fc_W);
    prep_k<<<dim3(BB, 4), 128>>>(enc, sep_mask);
    feats_k<<<BB * TT, 128>>>(pos_ids, pos_emb, wordlen_emb);

    // GEMM1: z = tanh(feats @ g_fcW^T + fc_b)  M=65536 N=200 K=592(padded)
    gemm_k<1, true><<<dim3(4, 512), 128>>>(
        d_feats, d_fcW, fc_b, nullptr, nullptr, nullptr, d_z,
        LIN, FPAD, FPAD, FPAD, LPAD, LPAD);

    // GEMM2: G0 = z @ W_ih^T + b_ih + b_hh     M=65536 N=1024 K=200
    gemm_k<2, false><<<dim3(16, 512), 128>>>(
        d_z, W_ih, b_ih, b_hh, nullptr, nullptr, d_G0,
        G4, LIN, LPAD, LIN, G4, G4);

    // LSTM recurrence (persistent, RED barrier, FFMA2)
    const int lstm_smem = 2 * 32 * 260 * (int)sizeof(float);
    cudaFuncSetAttribute(lstm_k, cudaFuncAttributeMaxDynamicSharedMemorySize, lstm_smem);
    lstm_k<<<NB_LSTM, 256, lstm_smem>>>(W_hh);

    // GEMM3: logits = [hs|enc] @ combine_W^T + mask   M=65536 N=58 K=768
    gemm_k<3, true><<<dim3(1, 512), 128>>>(
        d_hs, combine_W, nullptr, nullptr, enc, length, out,
        SP, KV, 0, KV, SP, SP);
}